// round 1
// baseline (speedup 1.0000x reference)
#include <cuda_runtime.h>
#include <cuda_bf16.h>
#include <math.h>

// Problem constants
#define NN 4096
#define FF 128
#define HH 128
#define KK 4
#define CC 10
#define H4 512
#define MAXNB 256

// ---------------- scratch (device globals; no runtime allocation) ----------------
__device__ float g_dinv[NN * KK];
__device__ int   g_cnt[NN * KK];
__device__ int   g_cols[(size_t)NN * KK * MAXNB];
__device__ float g_T[NN * HH];
__device__ float g_h1[NN * HH];
__device__ float g_gnn[(size_t)NN * KK * HH];
__device__ float g_XGf[(size_t)NN * KK * H4];
__device__ float g_XGb[(size_t)NN * KK * H4];
__device__ float g_Hh[(size_t)NN * H4];
__device__ float g_hbuf[NN * HH];
__device__ float g_cbuf[NN * HH];
__device__ float g_hfwd[(size_t)NN * KK * HH];
__device__ float g_hbwd[(size_t)NN * KK * HH];

// ---------------- adjacency scan: build neighbor lists + dinv ----------------
// adj layout [N, N, K] with K innermost -> one float4 per (n, j).
__global__ void extract_kernel(const float* __restrict__ adj) {
    int n = blockIdx.x;
    __shared__ int scnt[KK];
    if (threadIdx.x < KK) scnt[threadIdx.x] = 0;
    __syncthreads();
    const float4* row = (const float4*)(adj + (size_t)n * NN * KK);
    for (int j = threadIdx.x; j < NN; j += blockDim.x) {
        float4 v = row[j];
        if (v.x > 0.5f) { int p = atomicAdd(&scnt[0], 1); if (p < MAXNB) g_cols[((size_t)(n * KK + 0)) * MAXNB + p] = j; }
        if (v.y > 0.5f) { int p = atomicAdd(&scnt[1], 1); if (p < MAXNB) g_cols[((size_t)(n * KK + 1)) * MAXNB + p] = j; }
        if (v.z > 0.5f) { int p = atomicAdd(&scnt[2], 1); if (p < MAXNB) g_cols[((size_t)(n * KK + 2)) * MAXNB + p] = j; }
        if (v.w > 0.5f) { int p = atomicAdd(&scnt[3], 1); if (p < MAXNB) g_cols[((size_t)(n * KK + 3)) * MAXNB + p] = j; }
    }
    __syncthreads();
    if (threadIdx.x < KK) {
        int m = scnt[threadIdx.x];
        if (m > MAXNB) m = MAXNB;
        g_cnt[n * KK + threadIdx.x] = m;
        g_dinv[n * KK + threadIdx.x] = rsqrtf((float)m + 1.0f);
    }
}

// ---------------- SpMM: out[n, :] = dinv[n] * (dinv[n]*x[n,:] + sum_j dinv[j]*x[j,:]) + bias ----------------
__global__ void spmm_kernel(const float* __restrict__ x, const float* __restrict__ bias,
                            float* __restrict__ out, int k, int ostride, int ooff) {
    int n = blockIdx.x;
    int c = threadIdx.x;  // 128 threads
    __shared__ int scols[MAXNB];
    __shared__ float sw[MAXNB];
    int m = g_cnt[n * KK + k];
    float dn = g_dinv[n * KK + k];
    const int* cl = &g_cols[((size_t)(n * KK + k)) * MAXNB];
    for (int i = threadIdx.x; i < m; i += blockDim.x) {
        int j = cl[i];
        scols[i] = j;
        sw[i] = g_dinv[j * KK + k];
    }
    __syncthreads();
    float acc = dn * x[(size_t)n * HH + c];          // self loop
    for (int i = 0; i < m; i++)
        acc += sw[i] * x[(size_t)scols[i] * HH + c];
    out[(size_t)n * ostride + ooff + c] = dn * acc + bias[c];
}

// ---------------- generic fp32 tiled GEMM: C = A(MxKd) @ op(B) (+bias1+bias2) ----------------
// TRANSB=false: B is Kd x Nn row-major.  TRANSB=true: B is Nn x Kd row-major (C = A @ B^T).
// M, Nn multiples of 64; Kd multiple of 16 (all true here).
template <bool TRANSB>
__global__ void gemm_kernel(const float* __restrict__ A, const float* __restrict__ B,
                            const float* __restrict__ bias1, const float* __restrict__ bias2,
                            float* __restrict__ C, int M, int Nn, int Kd) {
    __shared__ float As[16][68];
    __shared__ float Bs[16][68];
    int bm = blockIdx.y * 64, bn = blockIdx.x * 64;
    int tid = threadIdx.x;
    int tx = tid & 15, ty = tid >> 4;
    float acc[4][4] = {};
    for (int k0 = 0; k0 < Kd; k0 += 16) {
        {
            int r = tid >> 2, c4 = (tid & 3) * 4;
            float4 v = *(const float4*)&A[(size_t)(bm + r) * Kd + k0 + c4];
            As[c4 + 0][r] = v.x; As[c4 + 1][r] = v.y; As[c4 + 2][r] = v.z; As[c4 + 3][r] = v.w;
        }
        if (!TRANSB) {
            int kk = tid >> 4, n4 = (tid & 15) * 4;
            float4 v = *(const float4*)&B[(size_t)(k0 + kk) * Nn + bn + n4];
            *(float4*)&Bs[kk][n4] = v;
        } else {
            int r = tid >> 2, c4 = (tid & 3) * 4;
            float4 v = *(const float4*)&B[(size_t)(bn + r) * Kd + k0 + c4];
            Bs[c4 + 0][r] = v.x; Bs[c4 + 1][r] = v.y; Bs[c4 + 2][r] = v.z; Bs[c4 + 3][r] = v.w;
        }
        __syncthreads();
#pragma unroll
        for (int kk = 0; kk < 16; kk++) {
            float a[4], b[4];
#pragma unroll
            for (int i = 0; i < 4; i++) a[i] = As[kk][ty * 4 + i];
#pragma unroll
            for (int j = 0; j < 4; j++) b[j] = Bs[kk][tx * 4 + j];
#pragma unroll
            for (int i = 0; i < 4; i++)
#pragma unroll
                for (int j = 0; j < 4; j++)
                    acc[i][j] = fmaf(a[i], b[j], acc[i][j]);
        }
        __syncthreads();
    }
#pragma unroll
    for (int i = 0; i < 4; i++) {
        int row = bm + ty * 4 + i;
#pragma unroll
        for (int j = 0; j < 4; j++) {
            int col = bn + tx * 4 + j;
            float v = acc[i][j];
            if (bias1) v += bias1[col];
            if (bias2) v += bias2[col];
            C[(size_t)row * Nn + col] = v;
        }
    }
}

// ---------------- LSTM gate fusion (one step) ----------------
__global__ void lstm_gate_kernel(const float* __restrict__ XG, const float* __restrict__ Hh,
                                 float* __restrict__ hbuf, float* __restrict__ cbuf,
                                 float* __restrict__ hout, int t, int first) {
    int idx = blockIdx.x * blockDim.x + threadIdx.x;  // N*H threads
    int n = idx >> 7, c = idx & 127;
    size_t base = ((size_t)n * KK + t) * H4;
    float gi = XG[base + c];
    float gf = XG[base + HH + c];
    float gg = XG[base + 2 * HH + c];
    float go = XG[base + 3 * HH + c];
    if (!first) {
        size_t hb = (size_t)n * H4;
        gi += Hh[hb + c];
        gf += Hh[hb + HH + c];
        gg += Hh[hb + 2 * HH + c];
        go += Hh[hb + 3 * HH + c];
    }
    float ig = 1.0f / (1.0f + expf(-gi));
    float fg = 1.0f / (1.0f + expf(-gf));
    float gv = tanhf(gg);
    float og = 1.0f / (1.0f + expf(-go));
    float cp = first ? 0.0f : cbuf[idx];
    float cn = fg * cp + ig * gv;
    float hn = og * tanhf(cn);
    cbuf[idx] = cn;
    hbuf[idx] = hn;
    hout[((size_t)n * KK + t) * HH + c] = hn;
}

// ---------------- attention + pooling + classifier + softmax ----------------
__global__ void final_kernel(const float* __restrict__ rw, const float* __restrict__ rb,
                             const float* __restrict__ ow, const float* __restrict__ ob,
                             float* __restrict__ out) {
    int n = blockIdx.x;
    int t = threadIdx.x;  // 128
    __shared__ float red[4];
    __shared__ float sattn[KK];
    __shared__ float sp[HH];
    __shared__ float sl[16];

    // attention logits e_k = <h_fwd, rw[0:H]> + <h_bwd, rw[H:2H]> + rb
    for (int k = 0; k < KK; k++) {
        float p = g_hfwd[((size_t)n * KK + k) * HH + t] * rw[t]
                + g_hbwd[((size_t)n * KK + k) * HH + t] * rw[HH + t];
        for (int o = 16; o; o >>= 1) p += __shfl_down_sync(0xffffffffu, p, o);
        if ((t & 31) == 0) red[t >> 5] = p;
        __syncthreads();
        if (t == 0) sattn[k] = red[0] + red[1] + red[2] + red[3] + rb[0];
        __syncthreads();
    }
    // softmax over K (thread 0)
    if (t == 0) {
        float m = sattn[0];
        for (int k = 1; k < KK; k++) m = fmaxf(m, sattn[k]);
        float s = 0.0f;
        for (int k = 0; k < KK; k++) { sattn[k] = expf(sattn[k] - m); s += sattn[k]; }
        float inv = 1.0f / s;
        for (int k = 0; k < KK; k++) sattn[k] *= inv;
    }
    __syncthreads();
    // pooled
    float pooled = 0.0f;
    for (int k = 0; k < KK; k++)
        pooled += sattn[k] * g_gnn[((size_t)n * KK + k) * HH + t];
    sp[t] = pooled;
    __syncthreads();
    // classifier logits: warp w handles classes c = w, w+4, ...
    int w = t >> 5, lane = t & 31;
    for (int c = w; c < CC; c += 4) {
        float s = sp[lane] * ow[c * HH + lane]
                + sp[lane + 32] * ow[c * HH + lane + 32]
                + sp[lane + 64] * ow[c * HH + lane + 64]
                + sp[lane + 96] * ow[c * HH + lane + 96];
        for (int o = 16; o; o >>= 1) s += __shfl_down_sync(0xffffffffu, s, o);
        if (lane == 0) sl[c] = s + ob[c];
    }
    __syncthreads();
    if (t == 0) {
        float m = sl[0];
        for (int c = 1; c < CC; c++) m = fmaxf(m, sl[c]);
        float s = 0.0f;
        for (int c = 0; c < CC; c++) { sl[c] = expf(sl[c] - m); s += sl[c]; }
        float inv = 1.0f / s;
        for (int c = 0; c < CC; c++) out[(size_t)n * CC + c] = sl[c] * inv;
    }
}

// ---------------- host orchestration ----------------
extern "C" void kernel_launch(void* const* d_in, const int* in_sizes, int n_in,
                              void* d_out, int out_size) {
    const float* feat  = (const float*)d_in[0];
    const float* adj   = (const float*)d_in[1];
    const float* w1    = (const float*)d_in[2];
    const float* b1    = (const float*)d_in[3];
    const float* w2    = (const float*)d_in[4];
    const float* b2    = (const float*)d_in[5];
    const float* wih_f = (const float*)d_in[6];
    const float* whh_f = (const float*)d_in[7];
    const float* bih_f = (const float*)d_in[8];
    const float* bhh_f = (const float*)d_in[9];
    const float* wih_b = (const float*)d_in[10];
    const float* whh_b = (const float*)d_in[11];
    const float* bih_b = (const float*)d_in[12];
    const float* bhh_b = (const float*)d_in[13];
    const float* rw    = (const float*)d_in[14];
    const float* rb    = (const float*)d_in[15];
    const float* ow    = (const float*)d_in[16];
    const float* ob    = (const float*)d_in[17];
    float* out = (float*)d_out;

    float *dT, *dh1, *dgnn, *dXGf, *dXGb, *dHh, *dhbuf, *dcbuf, *dhf, *dhb;
    cudaGetSymbolAddress((void**)&dT,    g_T);
    cudaGetSymbolAddress((void**)&dh1,   g_h1);
    cudaGetSymbolAddress((void**)&dgnn,  g_gnn);
    cudaGetSymbolAddress((void**)&dXGf,  g_XGf);
    cudaGetSymbolAddress((void**)&dXGb,  g_XGb);
    cudaGetSymbolAddress((void**)&dHh,   g_Hh);
    cudaGetSymbolAddress((void**)&dhbuf, g_hbuf);
    cudaGetSymbolAddress((void**)&dcbuf, g_cbuf);
    cudaGetSymbolAddress((void**)&dhf,   g_hfwd);
    cudaGetSymbolAddress((void**)&dhb,   g_hbwd);

    // 1) adjacency -> neighbor lists + dinv (resets counts every call; deterministic)
    extract_kernel<<<NN, 256>>>(adj);

    // 2) GCN blocks
    dim3 gH(HH / 64, NN / 64);
    for (int k = 0; k < KK; k++) {
        gemm_kernel<false><<<gH, 256>>>(feat, w1 + (size_t)k * FF * HH, nullptr, nullptr, dT, NN, HH, FF);
        spmm_kernel<<<NN, 128>>>(dT, b1 + k * HH, dh1, k, HH, 0);
        gemm_kernel<false><<<gH, 256>>>(dh1, w2 + (size_t)k * HH * HH, nullptr, nullptr, dT, NN, HH, HH);
        spmm_kernel<<<NN, 128>>>(dT, b2 + k * HH, dgnn, k, KK * HH, k * HH);
    }

    // 3) LSTM input precompute: XG = gnn_flat @ Wih^T + (bih + bhh)
    dim3 gXG(H4 / 64, (NN * KK) / 64);
    gemm_kernel<true><<<gXG, 256>>>(dgnn, wih_f, bih_f, bhh_f, dXGf, NN * KK, H4, HH);
    gemm_kernel<true><<<gXG, 256>>>(dgnn, wih_b, bih_b, bhh_b, dXGb, NN * KK, H4, HH);

    // 4) LSTM forward (t = 0..3)
    dim3 gR(H4 / 64, NN / 64);
    for (int t = 0; t < KK; t++) {
        if (t > 0)
            gemm_kernel<true><<<gR, 256>>>(dhbuf, whh_f, nullptr, nullptr, dHh, NN, H4, HH);
        lstm_gate_kernel<<<(NN * HH) / 256, 256>>>(dXGf, dHh, dhbuf, dcbuf, dhf, t, t == 0);
    }
    // 5) LSTM backward (t = 3..0)
    for (int s = 0; s < KK; s++) {
        int t = KK - 1 - s;
        if (s > 0)
            gemm_kernel<true><<<gR, 256>>>(dhbuf, whh_b, nullptr, nullptr, dHh, NN, H4, HH);
        lstm_gate_kernel<<<(NN * HH) / 256, 256>>>(dXGb, dHh, dhbuf, dcbuf, dhb, t, s == 0);
    }

    // 6) attention + pooling + classifier
    final_kernel<<<NN, 128>>>(rw, rb, ow, ob, out);

    (void)in_sizes; (void)n_in; (void)out_size;
}

// round 3
// speedup vs baseline: 1.2549x; 1.2549x over previous
#include <cuda_runtime.h>
#include <cuda_bf16.h>
#include <mma.h>
#include <math.h>

using namespace nvcuda;

// Problem constants
#define NN 4096
#define FF 128
#define HH 128
#define KK 4
#define CC 10
#define H4 512
#define MAXNB 256

// ---------------- scratch (device globals; no runtime allocation) ----------------
__device__ float g_dinv[NN * KK];
__device__ int   g_cnt[NN * KK];
__device__ int   g_cols[(size_t)NN * KK * MAXNB];
__device__ float g_T1[(size_t)KK * NN * HH];
__device__ float g_h1[(size_t)KK * NN * HH];
__device__ float g_T2[(size_t)KK * NN * HH];
__device__ float g_gnn[(size_t)NN * KK * HH];
__device__ float g_XG[(size_t)2 * NN * KK * H4];
__device__ float g_Hh[(size_t)NN * H4];
__device__ float g_hbuf[NN * HH];
__device__ float g_cbuf[NN * HH];
__device__ float g_hfwd[(size_t)NN * KK * HH];
__device__ float g_hbwd[(size_t)NN * KK * HH];

// ============================================================================
// wmma bf16 split-precision GEMM.
// C[M x N] = A[M x 128] @ B  (fp32 in/out; K = 128 fixed)
// BCOL=0: B is [K x N] row-major (ldb = row stride)
// BCOL=1: B is [N x K] row-major, used as B^T (K-major loads, ldb = row stride)
// fp32 -> bf16 hi/lo split; 3 MMA passes: hi*hi + hi*lo + lo*hi.
// grid: (N/128, M/128, Z); block: 256 threads (8 warps, each 32x64 of C).
// ============================================================================
#define LDA 40
#define LDBR 136
#define LDBC 40

__device__ __forceinline__ void split_st(__nv_bfloat16* hi, __nv_bfloat16* lo,
                                         int idx, float x0, float x1) {
    __nv_bfloat16 h0 = __float2bfloat16(x0);
    __nv_bfloat16 h1 = __float2bfloat16(x1);
    __nv_bfloat16 l0 = __float2bfloat16(x0 - __bfloat162float(h0));
    __nv_bfloat16 l1 = __float2bfloat16(x1 - __bfloat162float(h1));
    *(__nv_bfloat162*)(hi + idx) = __halves2bfloat162(h0, h1);
    *(__nv_bfloat162*)(lo + idx) = __halves2bfloat162(l0, l1);
}

template <int BCOL>
__global__ __launch_bounds__(256)
void wmma_gemm(const float* __restrict__ A, long a_zrows,
               const float* __restrict__ B0, const float* __restrict__ B1,
               long b_zstride, int ldb,
               float* __restrict__ C, long c_zstride, int ldc) {
    constexpr int LDB = BCOL ? LDBC : LDBR;
    constexpr int BELEMS = BCOL ? 128 * LDBC : 32 * LDBR;
    __shared__ __align__(16) __nv_bfloat16 Ahi[128 * LDA];
    __shared__ __align__(16) __nv_bfloat16 Alo[128 * LDA];
    __shared__ __align__(16) __nv_bfloat16 Bhi[BELEMS];
    __shared__ __align__(16) __nv_bfloat16 Blo[BELEMS];

    int tid = threadIdx.x;
    int z = blockIdx.z;
    int bn = blockIdx.x * 128;
    long arow0 = (long)blockIdx.y * 128 + (long)z * a_zrows;
    const float* Ap = A + arow0 * 128;
    const float* Bp = (B1 && z) ? B1 : (B0 + (size_t)z * b_zstride);

    int w = tid >> 5;
    int wm = (w & 3) * 32;       // warp row offset in C tile
    int wn = (w >> 2) * 64;      // warp col offset in C tile

    wmma::fragment<wmma::accumulator, 16, 16, 16, float> acc[2][4];
#pragma unroll
    for (int i = 0; i < 2; i++)
#pragma unroll
        for (int j = 0; j < 4; j++)
            wmma::fill_fragment(acc[i][j], 0.0f);

    for (int k0 = 0; k0 < 128; k0 += 32) {
        // ---- load + split A chunk [128 x 32] ----
        for (int i = tid; i < 1024; i += 256) {
            int r = i >> 3, c4 = (i & 7) * 4;
            float4 v = *(const float4*)(Ap + (size_t)r * 128 + k0 + c4);
            split_st(Ahi, Alo, r * LDA + c4, v.x, v.y);
            split_st(Ahi, Alo, r * LDA + c4 + 2, v.z, v.w);
        }
        // ---- load + split B chunk ----
        if (!BCOL) {
            // [32 x 128] rows k0..k0+31, cols bn..bn+127
            for (int i = tid; i < 1024; i += 256) {
                int r = i >> 5, c4 = (i & 31) * 4;
                float4 v = *(const float4*)(Bp + (size_t)(k0 + r) * ldb + bn + c4);
                split_st(Bhi, Blo, r * LDBR + c4, v.x, v.y);
                split_st(Bhi, Blo, r * LDBR + c4 + 2, v.z, v.w);
            }
        } else {
            // B^T: rows n = bn..bn+127 of [N x K], cols k0..k0+31
            for (int i = tid; i < 1024; i += 256) {
                int n = i >> 3, k4 = (i & 7) * 4;
                float4 v = *(const float4*)(Bp + (size_t)(bn + n) * ldb + k0 + k4);
                split_st(Bhi, Blo, n * LDBC + k4, v.x, v.y);
                split_st(Bhi, Blo, n * LDBC + k4 + 2, v.z, v.w);
            }
        }
        __syncthreads();

#pragma unroll
        for (int kk = 0; kk < 32; kk += 16) {
            wmma::fragment<wmma::matrix_a, 16, 16, 16, __nv_bfloat16, wmma::row_major> ah[2], al[2];
#pragma unroll
            for (int i = 0; i < 2; i++) {
                wmma::load_matrix_sync(ah[i], &Ahi[(wm + 16 * i) * LDA + kk], LDA);
                wmma::load_matrix_sync(al[i], &Alo[(wm + 16 * i) * LDA + kk], LDA);
            }
            if (!BCOL) {
                wmma::fragment<wmma::matrix_b, 16, 16, 16, __nv_bfloat16, wmma::row_major> bh[4], bl[4];
#pragma unroll
                for (int j = 0; j < 4; j++) {
                    wmma::load_matrix_sync(bh[j], &Bhi[kk * LDBR + wn + 16 * j], LDBR);
                    wmma::load_matrix_sync(bl[j], &Blo[kk * LDBR + wn + 16 * j], LDBR);
                }
#pragma unroll
                for (int i = 0; i < 2; i++)
#pragma unroll
                    for (int j = 0; j < 4; j++) {
                        wmma::mma_sync(acc[i][j], ah[i], bh[j], acc[i][j]);
                        wmma::mma_sync(acc[i][j], ah[i], bl[j], acc[i][j]);
                        wmma::mma_sync(acc[i][j], al[i], bh[j], acc[i][j]);
                    }
            } else {
                wmma::fragment<wmma::matrix_b, 16, 16, 16, __nv_bfloat16, wmma::col_major> bh[4], bl[4];
#pragma unroll
                for (int j = 0; j < 4; j++) {
                    wmma::load_matrix_sync(bh[j], &Bhi[(wn + 16 * j) * LDBC + kk], LDBC);
                    wmma::load_matrix_sync(bl[j], &Blo[(wn + 16 * j) * LDBC + kk], LDBC);
                }
#pragma unroll
                for (int i = 0; i < 2; i++)
#pragma unroll
                    for (int j = 0; j < 4; j++) {
                        wmma::mma_sync(acc[i][j], ah[i], bh[j], acc[i][j]);
                        wmma::mma_sync(acc[i][j], ah[i], bl[j], acc[i][j]);
                        wmma::mma_sync(acc[i][j], al[i], bh[j], acc[i][j]);
                    }
            }
        }
        __syncthreads();
    }

    // ---- epilogue: direct store (no bias; biases folded into consumers) ----
    float* Cp = C + (size_t)z * c_zstride + ((size_t)blockIdx.y * 128) * ldc + bn;
#pragma unroll
    for (int i = 0; i < 2; i++)
#pragma unroll
        for (int j = 0; j < 4; j++)
            wmma::store_matrix_sync(&Cp[(size_t)(wm + 16 * i) * ldc + wn + 16 * j],
                                    acc[i][j], ldc, wmma::mem_row_major);
}

// ---------------- adjacency scan: build neighbor lists + dinv ----------------
__global__ void extract_kernel(const float* __restrict__ adj) {
    int n = blockIdx.x;
    __shared__ int scnt[KK];
    if (threadIdx.x < KK) scnt[threadIdx.x] = 0;
    __syncthreads();
    const float4* row = (const float4*)(adj + (size_t)n * NN * KK);
    for (int j = threadIdx.x; j < NN; j += blockDim.x) {
        float4 v = row[j];
        if (v.x > 0.5f) { int p = atomicAdd(&scnt[0], 1); if (p < MAXNB) g_cols[((size_t)(n * KK + 0)) * MAXNB + p] = j; }
        if (v.y > 0.5f) { int p = atomicAdd(&scnt[1], 1); if (p < MAXNB) g_cols[((size_t)(n * KK + 1)) * MAXNB + p] = j; }
        if (v.z > 0.5f) { int p = atomicAdd(&scnt[2], 1); if (p < MAXNB) g_cols[((size_t)(n * KK + 2)) * MAXNB + p] = j; }
        if (v.w > 0.5f) { int p = atomicAdd(&scnt[3], 1); if (p < MAXNB) g_cols[((size_t)(n * KK + 3)) * MAXNB + p] = j; }
    }
    __syncthreads();
    if (threadIdx.x < KK) {
        int m = scnt[threadIdx.x];
        if (m > MAXNB) m = MAXNB;
        g_cnt[n * KK + threadIdx.x] = m;
        g_dinv[n * KK + threadIdx.x] = rsqrtf((float)m + 1.0f);
    }
}

// ---------------- SpMM (batched over k via blockIdx.y) ----------------
__global__ void spmm_kernel(const float* __restrict__ x, const float* __restrict__ bias,
                            float* __restrict__ out, long os_n, long os_k) {
    int n = blockIdx.x;
    int k = blockIdx.y;
    int c = threadIdx.x;  // 128 threads
    __shared__ int scols[MAXNB];
    __shared__ float sw[MAXNB];
    int m = g_cnt[n * KK + k];
    float dn = g_dinv[n * KK + k];
    const int* cl = &g_cols[((size_t)(n * KK + k)) * MAXNB];
    for (int i = threadIdx.x; i < m; i += blockDim.x) {
        int j = cl[i];
        scols[i] = j;
        sw[i] = g_dinv[j * KK + k];
    }
    __syncthreads();
    const float* xk = x + (size_t)k * NN * HH;
    float acc = dn * xk[(size_t)n * HH + c];
    for (int i = 0; i < m; i++)
        acc += sw[i] * xk[(size_t)scols[i] * HH + c];
    out[(size_t)n * os_n + (size_t)k * os_k + c] = dn * acc + bias[k * HH + c];
}

// ---------------- LSTM gate fusion (one step; adds input biases) ----------------
__global__ void lstm_gate_kernel(const float* __restrict__ XG, const float* __restrict__ Hh,
                                 const float* __restrict__ bi, const float* __restrict__ bh,
                                 float* __restrict__ hbuf, float* __restrict__ cbuf,
                                 float* __restrict__ hout, int t, int first) {
    int idx = blockIdx.x * blockDim.x + threadIdx.x;  // N*H threads
    int n = idx >> 7, c = idx & 127;
    size_t base = ((size_t)n * KK + t) * H4;
    float gi = XG[base + c]           + bi[c]           + bh[c];
    float gf = XG[base + HH + c]      + bi[HH + c]      + bh[HH + c];
    float gg = XG[base + 2 * HH + c]  + bi[2 * HH + c]  + bh[2 * HH + c];
    float go = XG[base + 3 * HH + c]  + bi[3 * HH + c]  + bh[3 * HH + c];
    if (!first) {
        size_t hb = (size_t)n * H4;
        gi += Hh[hb + c];
        gf += Hh[hb + HH + c];
        gg += Hh[hb + 2 * HH + c];
        go += Hh[hb + 3 * HH + c];
    }
    float ig = 1.0f / (1.0f + expf(-gi));
    float fg = 1.0f / (1.0f + expf(-gf));
    float gv = tanhf(gg);
    float og = 1.0f / (1.0f + expf(-go));
    float cp = first ? 0.0f : cbuf[idx];
    float cn = fg * cp + ig * gv;
    float hn = og * tanhf(cn);
    cbuf[idx] = cn;
    hbuf[idx] = hn;
    hout[((size_t)n * KK + t) * HH + c] = hn;
}

// ---------------- attention + pooling + classifier + softmax ----------------
__global__ void final_kernel(const float* __restrict__ rw, const float* __restrict__ rb,
                             const float* __restrict__ ow, const float* __restrict__ ob,
                             float* __restrict__ out) {
    int n = blockIdx.x;
    int t = threadIdx.x;  // 128
    __shared__ float red[4];
    __shared__ float sattn[KK];
    __shared__ float sp[HH];
    __shared__ float sl[16];

    for (int k = 0; k < KK; k++) {
        float p = g_hfwd[((size_t)n * KK + k) * HH + t] * rw[t]
                + g_hbwd[((size_t)n * KK + k) * HH + t] * rw[HH + t];
        for (int o = 16; o; o >>= 1) p += __shfl_down_sync(0xffffffffu, p, o);
        if ((t & 31) == 0) red[t >> 5] = p;
        __syncthreads();
        if (t == 0) sattn[k] = red[0] + red[1] + red[2] + red[3] + rb[0];
        __syncthreads();
    }
    if (t == 0) {
        float m = sattn[0];
        for (int k = 1; k < KK; k++) m = fmaxf(m, sattn[k]);
        float s = 0.0f;
        for (int k = 0; k < KK; k++) { sattn[k] = expf(sattn[k] - m); s += sattn[k]; }
        float inv = 1.0f / s;
        for (int k = 0; k < KK; k++) sattn[k] *= inv;
    }
    __syncthreads();
    float pooled = 0.0f;
    for (int k = 0; k < KK; k++)
        pooled += sattn[k] * g_gnn[((size_t)n * KK + k) * HH + t];
    sp[t] = pooled;
    __syncthreads();
    int w = t >> 5, lane = t & 31;
    for (int c = w; c < CC; c += 4) {
        float s = sp[lane] * ow[c * HH + lane]
                + sp[lane + 32] * ow[c * HH + lane + 32]
                + sp[lane + 64] * ow[c * HH + lane + 64]
                + sp[lane + 96] * ow[c * HH + lane + 96];
        for (int o = 16; o; o >>= 1) s += __shfl_down_sync(0xffffffffu, s, o);
        if (lane == 0) sl[c] = s + ob[c];
    }
    __syncthreads();
    if (t == 0) {
        float m = sl[0];
        for (int c = 1; c < CC; c++) m = fmaxf(m, sl[c]);
        float s = 0.0f;
        for (int c = 0; c < CC; c++) { sl[c] = expf(sl[c] - m); s += sl[c]; }
        float inv = 1.0f / s;
        for (int c = 0; c < CC; c++) out[(size_t)n * CC + c] = sl[c] * inv;
    }
}

// ---------------- host orchestration ----------------
extern "C" void kernel_launch(void* const* d_in, const int* in_sizes, int n_in,
                              void* d_out, int out_size) {
    const float* feat  = (const float*)d_in[0];
    const float* adj   = (const float*)d_in[1];
    const float* w1    = (const float*)d_in[2];
    const float* b1    = (const float*)d_in[3];
    const float* w2    = (const float*)d_in[4];
    const float* b2    = (const float*)d_in[5];
    const float* wih_f = (const float*)d_in[6];
    const float* whh_f = (const float*)d_in[7];
    const float* bih_f = (const float*)d_in[8];
    const float* bhh_f = (const float*)d_in[9];
    const float* wih_b = (const float*)d_in[10];
    const float* whh_b = (const float*)d_in[11];
    const float* bih_b = (const float*)d_in[12];
    const float* bhh_b = (const float*)d_in[13];
    const float* rw    = (const float*)d_in[14];
    const float* rb    = (const float*)d_in[15];
    const float* ow    = (const float*)d_in[16];
    const float* ob    = (const float*)d_in[17];
    float* out = (float*)d_out;

    float *dT1, *dh1, *dT2, *dgnn, *dXG, *dHh, *dhbuf, *dcbuf, *dhf, *dhb;
    cudaGetSymbolAddress((void**)&dT1,   g_T1);
    cudaGetSymbolAddress((void**)&dh1,   g_h1);
    cudaGetSymbolAddress((void**)&dT2,   g_T2);
    cudaGetSymbolAddress((void**)&dgnn,  g_gnn);
    cudaGetSymbolAddress((void**)&dXG,   g_XG);
    cudaGetSymbolAddress((void**)&dHh,   g_Hh);
    cudaGetSymbolAddress((void**)&dhbuf, g_hbuf);
    cudaGetSymbolAddress((void**)&dcbuf, g_cbuf);
    cudaGetSymbolAddress((void**)&dhf,   g_hfwd);
    cudaGetSymbolAddress((void**)&dhb,   g_hbwd);

    const long NH = (long)NN * HH;
    const long XGZ = (long)NN * KK * H4;

    // 1) adjacency -> neighbor lists + dinv
    extract_kernel<<<NN, 256>>>(adj);

    // 2) GCN layer 1 (4 blocks batched over z): T1[k] = feat @ w1[k]
    wmma_gemm<0><<<dim3(1, NN / 128, KK), 256>>>(
        feat, 0, w1, nullptr, (long)FF * HH, HH, dT1, NH, HH);
    spmm_kernel<<<dim3(NN, KK), 128>>>(dT1, b1, dh1, HH, NH);

    // 3) GCN layer 2: T2[k] = h1[k] @ w2[k]
    wmma_gemm<0><<<dim3(1, NN / 128, KK), 256>>>(
        dh1, NN, w2, nullptr, (long)HH * HH, HH, dT2, NH, HH);
    spmm_kernel<<<dim3(NN, KK), 128>>>(dT2, b2, dgnn, (long)KK * HH, HH);

    // 4) LSTM input precompute (both directions batched over z):
    //    XG[dir] = gnn_flat @ Wih^T (biases folded into gate kernel)
    wmma_gemm<1><<<dim3(H4 / 128, (NN * KK) / 128, 2), 256>>>(
        dgnn, 0, wih_f, wih_b, 0, HH, dXG, XGZ, H4);

    // 5) LSTM forward (t = 0..3)
    for (int t = 0; t < KK; t++) {
        if (t > 0)
            wmma_gemm<1><<<dim3(H4 / 128, NN / 128, 1), 256>>>(
                dhbuf, 0, whh_f, nullptr, 0, HH, dHh, 0, H4);
        lstm_gate_kernel<<<(NN * HH) / 256, 256>>>(dXG, dHh, bih_f, bhh_f,
                                                   dhbuf, dcbuf, dhf, t, t == 0);
    }
    // 6) LSTM backward (t = 3..0)
    for (int s = 0; s < KK; s++) {
        int t = KK - 1 - s;
        if (s > 0)
            wmma_gemm<1><<<dim3(H4 / 128, NN / 128, 1), 256>>>(
                dhbuf, 0, whh_b, nullptr, 0, HH, dHh, 0, H4);
        lstm_gate_kernel<<<(NN * HH) / 256, 256>>>(dXG + XGZ, dHh, bih_b, bhh_b,
                                                   dhbuf, dcbuf, dhb, t, s == 0);
    }

    // 7) attention + pooling + classifier
    final_kernel<<<NN, 128>>>(rw, rb, ow, ob, out);

    (void)in_sizes; (void)n_in; (void)out_size;
}

// round 4
// speedup vs baseline: 1.9658x; 1.5665x over previous
#include <cuda_runtime.h>
#include <cuda_bf16.h>
#include <mma.h>
#include <math.h>

using namespace nvcuda;

// Problem constants
#define NN 4096
#define FF 128
#define HH 128
#define KK 4
#define CC 10
#define H4 512
#define MAXNB 256

// ---------------- scratch (device globals; no runtime allocation) ----------------
__device__ float g_dinv[NN * KK];
__device__ int   g_cnt[NN * KK];
__device__ int   g_cols[(size_t)NN * KK * MAXNB];
__device__ float g_T1[(size_t)KK * NN * HH];
__device__ float g_h1[(size_t)KK * NN * HH];
__device__ float g_T2[(size_t)KK * NN * HH];
__device__ float g_gnn[(size_t)NN * KK * HH];
__device__ float g_XG[(size_t)2 * NN * KK * H4];
__device__ float g_Hh[(size_t)2 * NN * H4];
__device__ float g_hbuf[(size_t)2 * NN * HH];
__device__ float g_cbuf[(size_t)2 * NN * HH];
__device__ float g_hfwd[(size_t)NN * KK * HH];
__device__ float g_hbwd[(size_t)NN * KK * HH];

// ============================================================================
// wmma bf16 split-precision GEMM (one-shot K=128 staging).
// C[M x N] = A[M x 128] @ B  (fp32 in/out)
// BCOL=0: B is [K x N] row-major (ldb = row stride)
// BCOL=1: B is [N x K] row-major, used as B^T
// fp32 -> bf16 hi/lo split; 3 MMA passes: hi*hi + hi*lo + lo*hi.
// grid: (N/128, M/128, Z); block: 512 threads = 16 warps, each 32x32 of C.
// ============================================================================
#define LDS 136
#define TILE_ELEMS (128 * LDS)
#define SMEM_BYTES (4 * TILE_ELEMS * 2)

__device__ __forceinline__ void split_st(__nv_bfloat16* hi, __nv_bfloat16* lo,
                                         int idx, float x0, float x1) {
    __nv_bfloat16 h0 = __float2bfloat16(x0);
    __nv_bfloat16 h1 = __float2bfloat16(x1);
    __nv_bfloat16 l0 = __float2bfloat16(x0 - __bfloat162float(h0));
    __nv_bfloat16 l1 = __float2bfloat16(x1 - __bfloat162float(h1));
    *(__nv_bfloat162*)(hi + idx) = __halves2bfloat162(h0, h1);
    *(__nv_bfloat162*)(lo + idx) = __halves2bfloat162(l0, l1);
}

template <int BCOL>
__global__ __launch_bounds__(512)
void wmma_gemm(const float* __restrict__ A, long a_zrows,
               const float* __restrict__ B0, const float* __restrict__ B1,
               long b_zstride, int ldb,
               float* __restrict__ C, long c_zstride, int ldc) {
    extern __shared__ __nv_bfloat16 sm[];
    __nv_bfloat16* Ahi = sm;
    __nv_bfloat16* Alo = sm + TILE_ELEMS;
    __nv_bfloat16* Bhi = sm + 2 * TILE_ELEMS;
    __nv_bfloat16* Blo = sm + 3 * TILE_ELEMS;

    int tid = threadIdx.x;
    int z = blockIdx.z;
    int bn = blockIdx.x * 128;
    long arow0 = (long)blockIdx.y * 128 + (long)z * a_zrows;
    const float* Ap = A + arow0 * 128;
    const float* Bp = (B1 && z) ? B1 : (B0 + (size_t)z * b_zstride);

    // ---- stage A [128 x 128] ----
#pragma unroll
    for (int it = 0; it < 8; it++) {
        int i = tid + it * 512;
        int r = i >> 5, c4 = (i & 31) << 2;
        float4 v = *(const float4*)(Ap + (size_t)r * 128 + c4);
        split_st(Ahi, Alo, r * LDS + c4, v.x, v.y);
        split_st(Ahi, Alo, r * LDS + c4 + 2, v.z, v.w);
    }
    // ---- stage B ----
    if (!BCOL) {
#pragma unroll
        for (int it = 0; it < 8; it++) {
            int i = tid + it * 512;
            int r = i >> 5, c4 = (i & 31) << 2;
            float4 v = *(const float4*)(Bp + (size_t)r * ldb + bn + c4);
            split_st(Bhi, Blo, r * LDS + c4, v.x, v.y);
            split_st(Bhi, Blo, r * LDS + c4 + 2, v.z, v.w);
        }
    } else {
#pragma unroll
        for (int it = 0; it < 8; it++) {
            int i = tid + it * 512;
            int n = i >> 5, k4 = (i & 31) << 2;
            float4 v = *(const float4*)(Bp + (size_t)(bn + n) * ldb + k4);
            split_st(Bhi, Blo, n * LDS + k4, v.x, v.y);
            split_st(Bhi, Blo, n * LDS + k4 + 2, v.z, v.w);
        }
    }
    __syncthreads();

    int w = tid >> 5;
    int wm = (w & 3) * 32;    // warp row offset
    int wn = (w >> 2) * 32;   // warp col offset

    wmma::fragment<wmma::accumulator, 16, 16, 16, float> acc[2][2];
#pragma unroll
    for (int i = 0; i < 2; i++)
#pragma unroll
        for (int j = 0; j < 2; j++)
            wmma::fill_fragment(acc[i][j], 0.0f);

#pragma unroll
    for (int kk = 0; kk < 128; kk += 16) {
        wmma::fragment<wmma::matrix_a, 16, 16, 16, __nv_bfloat16, wmma::row_major> ah[2], al[2];
#pragma unroll
        for (int i = 0; i < 2; i++) {
            wmma::load_matrix_sync(ah[i], &Ahi[(wm + 16 * i) * LDS + kk], LDS);
            wmma::load_matrix_sync(al[i], &Alo[(wm + 16 * i) * LDS + kk], LDS);
        }
        if (!BCOL) {
            wmma::fragment<wmma::matrix_b, 16, 16, 16, __nv_bfloat16, wmma::row_major> bh[2], bl[2];
#pragma unroll
            for (int j = 0; j < 2; j++) {
                wmma::load_matrix_sync(bh[j], &Bhi[kk * LDS + wn + 16 * j], LDS);
                wmma::load_matrix_sync(bl[j], &Blo[kk * LDS + wn + 16 * j], LDS);
            }
#pragma unroll
            for (int i = 0; i < 2; i++)
#pragma unroll
                for (int j = 0; j < 2; j++) {
                    wmma::mma_sync(acc[i][j], ah[i], bh[j], acc[i][j]);
                    wmma::mma_sync(acc[i][j], ah[i], bl[j], acc[i][j]);
                    wmma::mma_sync(acc[i][j], al[i], bh[j], acc[i][j]);
                }
        } else {
            wmma::fragment<wmma::matrix_b, 16, 16, 16, __nv_bfloat16, wmma::col_major> bh[2], bl[2];
#pragma unroll
            for (int j = 0; j < 2; j++) {
                wmma::load_matrix_sync(bh[j], &Bhi[(wn + 16 * j) * LDS + kk], LDS);
                wmma::load_matrix_sync(bl[j], &Blo[(wn + 16 * j) * LDS + kk], LDS);
            }
#pragma unroll
            for (int i = 0; i < 2; i++)
#pragma unroll
                for (int j = 0; j < 2; j++) {
                    wmma::mma_sync(acc[i][j], ah[i], bh[j], acc[i][j]);
                    wmma::mma_sync(acc[i][j], ah[i], bl[j], acc[i][j]);
                    wmma::mma_sync(acc[i][j], al[i], bh[j], acc[i][j]);
                }
        }
    }

    // ---- epilogue: direct store (biases folded into consumers) ----
    float* Cp = C + (size_t)z * c_zstride + ((size_t)blockIdx.y * 128) * ldc + bn;
#pragma unroll
    for (int i = 0; i < 2; i++)
#pragma unroll
        for (int j = 0; j < 2; j++)
            wmma::store_matrix_sync(&Cp[(size_t)(wm + 16 * i) * ldc + wn + 16 * j],
                                    acc[i][j], ldc, wmma::mem_row_major);
}

// ---------------- adjacency scan: build neighbor lists + dinv ----------------
__global__ void extract_kernel(const float* __restrict__ adj) {
    int n = blockIdx.x;
    __shared__ int scnt[KK];
    if (threadIdx.x < KK) scnt[threadIdx.x] = 0;
    __syncthreads();
    const float4* row = (const float4*)(adj + (size_t)n * NN * KK);
    for (int j = threadIdx.x; j < NN; j += blockDim.x) {
        float4 v = row[j];
        if (v.x > 0.5f) { int p = atomicAdd(&scnt[0], 1); if (p < MAXNB) g_cols[((size_t)(n * KK + 0)) * MAXNB + p] = j; }
        if (v.y > 0.5f) { int p = atomicAdd(&scnt[1], 1); if (p < MAXNB) g_cols[((size_t)(n * KK + 1)) * MAXNB + p] = j; }
        if (v.z > 0.5f) { int p = atomicAdd(&scnt[2], 1); if (p < MAXNB) g_cols[((size_t)(n * KK + 2)) * MAXNB + p] = j; }
        if (v.w > 0.5f) { int p = atomicAdd(&scnt[3], 1); if (p < MAXNB) g_cols[((size_t)(n * KK + 3)) * MAXNB + p] = j; }
    }
    __syncthreads();
    if (threadIdx.x < KK) {
        int m = scnt[threadIdx.x];
        if (m > MAXNB) m = MAXNB;
        g_cnt[n * KK + threadIdx.x] = m;
        g_dinv[n * KK + threadIdx.x] = rsqrtf((float)m + 1.0f);
    }
}

// ---------------- SpMM (batched over k via blockIdx.y) ----------------
__global__ void spmm_kernel(const float* __restrict__ x, const float* __restrict__ bias,
                            float* __restrict__ out, long os_n, long os_k) {
    int n = blockIdx.x;
    int k = blockIdx.y;
    int c = threadIdx.x;  // 128 threads
    __shared__ int scols[MAXNB];
    __shared__ float sw[MAXNB];
    int m = g_cnt[n * KK + k];
    float dn = g_dinv[n * KK + k];
    const int* cl = &g_cols[((size_t)(n * KK + k)) * MAXNB];
    for (int i = threadIdx.x; i < m; i += blockDim.x) {
        int j = cl[i];
        scols[i] = j;
        sw[i] = g_dinv[j * KK + k];
    }
    __syncthreads();
    const float* xk = x + (size_t)k * NN * HH;
    float acc = dn * xk[(size_t)n * HH + c];
    for (int i = 0; i < m; i++)
        acc += sw[i] * xk[(size_t)scols[i] * HH + c];
    out[(size_t)n * os_n + (size_t)k * os_k + c] = dn * acc + bias[k * HH + c];
}

// ---------------- LSTM gate fusion, both directions batched (blockIdx.y = dir) ----------------
__global__ void lstm_gate_kernel(const float* __restrict__ XG, const float* __restrict__ Hh,
                                 const float* __restrict__ bi_f, const float* __restrict__ bh_f,
                                 const float* __restrict__ bi_b, const float* __restrict__ bh_b,
                                 float* __restrict__ hbuf, float* __restrict__ cbuf,
                                 float* __restrict__ hf, float* __restrict__ hb, int step) {
    int dir = blockIdx.y;
    int idx = blockIdx.x * blockDim.x + threadIdx.x;  // N*H threads
    int n = idx >> 7, c = idx & 127;
    int t = dir ? (KK - 1 - step) : step;
    int first = (step == 0);
    const float* xg = XG + (size_t)dir * NN * KK * H4;
    const float* bi = dir ? bi_b : bi_f;
    const float* bh = dir ? bh_b : bh_f;
    size_t base = ((size_t)n * KK + t) * H4;
    float gi = xg[base + c]          + bi[c]          + bh[c];
    float gf = xg[base + HH + c]     + bi[HH + c]     + bh[HH + c];
    float gg = xg[base + 2 * HH + c] + bi[2 * HH + c] + bh[2 * HH + c];
    float go = xg[base + 3 * HH + c] + bi[3 * HH + c] + bh[3 * HH + c];
    if (!first) {
        const float* hh = Hh + (size_t)dir * NN * H4 + (size_t)n * H4;
        gi += hh[c];
        gf += hh[HH + c];
        gg += hh[2 * HH + c];
        go += hh[3 * HH + c];
    }
    float ig = 1.0f / (1.0f + expf(-gi));
    float fg = 1.0f / (1.0f + expf(-gf));
    float gv = tanhf(gg);
    float og = 1.0f / (1.0f + expf(-go));
    size_t sidx = (size_t)dir * NN * HH + idx;
    float cp = first ? 0.0f : cbuf[sidx];
    float cn = fg * cp + ig * gv;
    float hn = og * tanhf(cn);
    cbuf[sidx] = cn;
    hbuf[sidx] = hn;
    float* hout = dir ? hb : hf;
    hout[((size_t)n * KK + t) * HH + c] = hn;
}

// ---------------- attention + pooling + classifier + softmax ----------------
__global__ void final_kernel(const float* __restrict__ rw, const float* __restrict__ rb,
                             const float* __restrict__ ow, const float* __restrict__ ob,
                             float* __restrict__ out) {
    int n = blockIdx.x;
    int t = threadIdx.x;  // 128
    __shared__ float red[4];
    __shared__ float sattn[KK];
    __shared__ float sp[HH];
    __shared__ float sl[16];

    for (int k = 0; k < KK; k++) {
        float p = g_hfwd[((size_t)n * KK + k) * HH + t] * rw[t]
                + g_hbwd[((size_t)n * KK + k) * HH + t] * rw[HH + t];
        for (int o = 16; o; o >>= 1) p += __shfl_down_sync(0xffffffffu, p, o);
        if ((t & 31) == 0) red[t >> 5] = p;
        __syncthreads();
        if (t == 0) sattn[k] = red[0] + red[1] + red[2] + red[3] + rb[0];
        __syncthreads();
    }
    if (t == 0) {
        float m = sattn[0];
        for (int k = 1; k < KK; k++) m = fmaxf(m, sattn[k]);
        float s = 0.0f;
        for (int k = 0; k < KK; k++) { sattn[k] = expf(sattn[k] - m); s += sattn[k]; }
        float inv = 1.0f / s;
        for (int k = 0; k < KK; k++) sattn[k] *= inv;
    }
    __syncthreads();
    float pooled = 0.0f;
    for (int k = 0; k < KK; k++)
        pooled += sattn[k] * g_gnn[((size_t)n * KK + k) * HH + t];
    sp[t] = pooled;
    __syncthreads();
    int w = t >> 5, lane = t & 31;
    for (int c = w; c < CC; c += 4) {
        float s = sp[lane] * ow[c * HH + lane]
                + sp[lane + 32] * ow[c * HH + lane + 32]
                + sp[lane + 64] * ow[c * HH + lane + 64]
                + sp[lane + 96] * ow[c * HH + lane + 96];
        for (int o = 16; o; o >>= 1) s += __shfl_down_sync(0xffffffffu, s, o);
        if (lane == 0) sl[c] = s + ob[c];
    }
    __syncthreads();
    if (t == 0) {
        float m = sl[0];
        for (int c = 1; c < CC; c++) m = fmaxf(m, sl[c]);
        float s = 0.0f;
        for (int c = 0; c < CC; c++) { sl[c] = expf(sl[c] - m); s += sl[c]; }
        float inv = 1.0f / s;
        for (int c = 0; c < CC; c++) out[(size_t)n * CC + c] = sl[c] * inv;
    }
}

// ---------------- host orchestration ----------------
extern "C" void kernel_launch(void* const* d_in, const int* in_sizes, int n_in,
                              void* d_out, int out_size) {
    const float* feat  = (const float*)d_in[0];
    const float* adj   = (const float*)d_in[1];
    const float* w1    = (const float*)d_in[2];
    const float* b1    = (const float*)d_in[3];
    const float* w2    = (const float*)d_in[4];
    const float* b2    = (const float*)d_in[5];
    const float* wih_f = (const float*)d_in[6];
    const float* whh_f = (const float*)d_in[7];
    const float* bih_f = (const float*)d_in[8];
    const float* bhh_f = (const float*)d_in[9];
    const float* wih_b = (const float*)d_in[10];
    const float* whh_b = (const float*)d_in[11];
    const float* bih_b = (const float*)d_in[12];
    const float* bhh_b = (const float*)d_in[13];
    const float* rw    = (const float*)d_in[14];
    const float* rb    = (const float*)d_in[15];
    const float* ow    = (const float*)d_in[16];
    const float* ob    = (const float*)d_in[17];
    float* out = (float*)d_out;

    float *dT1, *dh1, *dT2, *dgnn, *dXG, *dHh, *dhbuf, *dcbuf, *dhf, *dhb;
    cudaGetSymbolAddress((void**)&dT1,   g_T1);
    cudaGetSymbolAddress((void**)&dh1,   g_h1);
    cudaGetSymbolAddress((void**)&dT2,   g_T2);
    cudaGetSymbolAddress((void**)&dgnn,  g_gnn);
    cudaGetSymbolAddress((void**)&dXG,   g_XG);
    cudaGetSymbolAddress((void**)&dHh,   g_Hh);
    cudaGetSymbolAddress((void**)&dhbuf, g_hbuf);
    cudaGetSymbolAddress((void**)&dcbuf, g_cbuf);
    cudaGetSymbolAddress((void**)&dhf,   g_hfwd);
    cudaGetSymbolAddress((void**)&dhb,   g_hbwd);

    static int smem_set = 0;
    if (!smem_set) {
        cudaFuncSetAttribute((const void*)wmma_gemm<0>,
                             cudaFuncAttributeMaxDynamicSharedMemorySize, SMEM_BYTES);
        cudaFuncSetAttribute((const void*)wmma_gemm<1>,
                             cudaFuncAttributeMaxDynamicSharedMemorySize, SMEM_BYTES);
        smem_set = 1;
    }

    const long NH = (long)NN * HH;
    const long XGZ = (long)NN * KK * H4;

    // 1) adjacency -> neighbor lists + dinv
    extract_kernel<<<NN, 256>>>(adj);

    // 2) GCN layer 1 (4 blocks batched over z): T1[k] = feat @ w1[k]
    wmma_gemm<0><<<dim3(1, NN / 128, KK), 512, SMEM_BYTES>>>(
        feat, 0, w1, nullptr, (long)FF * HH, HH, dT1, NH, HH);
    spmm_kernel<<<dim3(NN, KK), 128>>>(dT1, b1, dh1, HH, NH);

    // 3) GCN layer 2: T2[k] = h1[k] @ w2[k]
    wmma_gemm<0><<<dim3(1, NN / 128, KK), 512, SMEM_BYTES>>>(
        dh1, NN, w2, nullptr, (long)HH * HH, HH, dT2, NH, HH);
    spmm_kernel<<<dim3(NN, KK), 128>>>(dT2, b2, dgnn, (long)KK * HH, HH);

    // 4) LSTM input precompute (both directions batched over z):
    //    XG[dir] = gnn_flat @ Wih^T (biases folded into gate kernel)
    wmma_gemm<1><<<dim3(H4 / 128, (NN * KK) / 128, 2), 512, SMEM_BYTES>>>(
        dgnn, 0, wih_f, wih_b, 0, HH, dXG, XGZ, H4);

    // 5) Bidirectional LSTM, 4 steps; fwd+bwd batched per step
    for (int step = 0; step < KK; step++) {
        if (step > 0)
            wmma_gemm<1><<<dim3(H4 / 128, NN / 128, 2), 512, SMEM_BYTES>>>(
                dhbuf, NN, whh_f, whh_b, 0, HH, dHh, (long)NN * H4, H4);
        lstm_gate_kernel<<<dim3((NN * HH) / 256, 2), 256>>>(
            dXG, dHh, bih_f, bhh_f, bih_b, bhh_b, dhbuf, dcbuf, dhf, dhb, step);
    }

    // 6) attention + pooling + classifier
    final_kernel<<<NN, 128>>>(rw, rb, ow, ob, out);

    (void)in_sizes; (void)n_in; (void)out_size;
}